// round 12
// baseline (speedup 1.0000x reference)
#include <cuda_runtime.h>
#include <cuda_fp16.h>
#include <math.h>

#define V 50257
#define H 1024
#define T 10
#define TB (T - 1)                       // batched steps 1..9
#define NLB_F ((V + 15) / 16)            // 3142: fp32 conv/batch blocks (16 rows)
#define NLB_S ((V + 31) / 32)            // 1571: fp16 screen blocks (32 rows)

// ---------------- device scratch (no allocations allowed) ----------------
__device__ __align__(16) float g_h[2][H];
__device__ __align__(16) float g_c[2][H];
__device__ __align__(16) float g_enc[T * H];
__device__ __align__(16) float g_prev[H];
__device__ __align__(16) float g_q[H];
__device__ __align__(16) float g_ctx[H];
__device__ __align__(16) float g_gate[4 * H];
__device__ __align__(16) float g_xproj[T * 4 * H];
__device__ __align__(16) float g_hist[T][H];     // h used at each decode step
__device__ int   g_tok[T];
__device__ float g_pval[2 * NLB_F + 32];
__device__ int   g_pidx[2 * NLB_F + 32];
__device__ unsigned int g_cnt1;
__device__ unsigned int g_cnt2;
__device__ int   g_wmax_bits;                    // global max|out_w|
__device__ __align__(16) __half g_w16[(size_t)V * H];  // fp16 sketch (~98MB)

__device__ __forceinline__ float sigm(float x) { return 1.f / (1.f + expf(-x)); }
__device__ __forceinline__ float dot4(float4 a, float4 b) {
    return a.x * b.x + a.y * b.y + a.z * b.z + a.w * b.w;
}

// ---------------- init ----------------------------------------------------
__global__ void k_init(const void* __restrict__ seq_raw,
                       float* __restrict__ out, int out_size) {
    int tid = blockIdx.x * blockDim.x + threadIdx.x;
    if (tid == 0) {
        const long long* s64 = (const long long*)seq_raw;
        bool ok64 = true;
        for (int i = 0; i < T; i++) {
            long long v = s64[i];
            if (v < 0 || v >= V) { ok64 = false; break; }
        }
        const int* s32 = (const int*)seq_raw;
        for (int i = 0; i < T; i++) g_tok[i] = ok64 ? (int)s64[i] : s32[i];
        g_cnt1 = 0; g_cnt2 = 0; g_wmax_bits = 0;
    }
    int stride = gridDim.x * blockDim.x;
    for (int i = tid; i < H; i += stride) {
        g_h[0][i] = 0.f; g_c[0][i] = 0.f; g_prev[i] = 0.f;
    }
    for (int i = tid; i < out_size; i += stride) out[i] = 0.f;
}

// ------- hoisted input projection -----------------------------------------
__global__ void k_xproj(const float* __restrict__ w_ih,
                        const float* __restrict__ b_ih,
                        const float* __restrict__ b_hh,
                        const float* __restrict__ embeds) {
    int tid  = threadIdx.x;
    int warp = tid >> 5;
    int lane = tid & 31;
    int j    = blockIdx.x * 2 + (warp >> 2);
    int gate = warp & 3;

    const float4* wi = (const float4*)w_ih + (size_t)(gate * H + j) * 256;
    float4 w[8];
#pragma unroll
    for (int i = 0; i < 8; i++) w[i] = wi[lane + 32 * i];

    float acc[T];
#pragma unroll
    for (int t = 0; t < T; t++) {
        const float4* x4 = (const float4*)(embeds + (size_t)g_tok[t] * H);
        float a = 0.f;
#pragma unroll
        for (int i = 0; i < 8; i++) a += dot4(w[i], x4[lane + 32 * i]);
        acc[t] = a;
    }
#pragma unroll
    for (int t = 0; t < T; t++)
        for (int off = 16; off > 0; off >>= 1)
            acc[t] += __shfl_down_sync(0xffffffffu, acc[t], off);
    if (lane == 0) {
        int row = gate * H + j;
        float b = b_ih[row] + b_hh[row];
#pragma unroll
        for (int t = 0; t < T; t++)
            g_xproj[t * 4 * H + row] = acc[t] + b;
    }
}

// ------- encoder step: W_hh@h only ----------------------------------------
__global__ void k_lstm_enc(const float* __restrict__ w_hh, int step, int bi) {
    int tid  = threadIdx.x;
    int warp = tid >> 5;
    int lane = tid & 31;
    int j    = blockIdx.x * 2 + (warp >> 2);
    int gate = warp & 3;

    const float4* h4 = (const float4*)g_h[bi];
    const float4* wh = (const float4*)w_hh + (size_t)(gate * H + j) * 256;

    float acc = 0.f;
#pragma unroll
    for (int i = 0; i < 8; i++) {
        int k = lane + 32 * i;
        acc += dot4(wh[k], h4[k]);
    }
    for (int off = 16; off > 0; off >>= 1)
        acc += __shfl_down_sync(0xffffffffu, acc, off);

    __shared__ float s[8];
    if (lane == 0) s[warp] = acc;
    __syncthreads();
    if (tid < 2) {
        int u = blockIdx.x * 2 + tid;
        const float* xp = g_xproj + step * 4 * H;
        float gi = s[tid * 4 + 0] + xp[u];
        float gf = s[tid * 4 + 1] + xp[H + u];
        float gg = s[tid * 4 + 2] + xp[2 * H + u];
        float go = s[tid * 4 + 3] + xp[3 * H + u];
        float i_ = sigm(gi), f_ = sigm(gf), g_ = tanhf(gg), o_ = sigm(go);
        float cn = f_ * g_c[bi][u] + i_ * g_;
        float hn = o_ * tanhf(cn);
        g_c[1 - bi][u] = cn;
        g_h[1 - bi][u] = hn;
        g_enc[step * H + u] = hn;
    }
}

// ---------------- q = wa^T h, last block does softmax+ctx -----------------
__global__ void k_qattn(const float* __restrict__ wa, int bi) {
    int tid  = threadIdx.x;
    int lane = tid & 31;
    int warp = tid >> 5;
    int col  = blockIdx.x * 32 + lane;
    const float* h = g_h[bi];

    float acc = 0.f;
    for (int i = warp; i < H; i += 8) acc += h[i] * wa[(size_t)i * H + col];
    __shared__ float s[256];
    s[tid] = acc;
    __syncthreads();
    for (int off = 128; off >= 32; off >>= 1) {
        if (tid < off) s[tid] += s[tid + off];
        __syncthreads();
    }
    if (tid < 32) g_q[col] = s[tid];

    __shared__ int s_last;
    __threadfence();
    if (tid == 0) s_last = (atomicAdd(&g_cnt1, 1u) == gridDim.x - 1);
    __syncthreads();
    if (!s_last) return;
    if (tid == 0) g_cnt1 = 0;

    float at[T];
#pragma unroll
    for (int t = 0; t < T; t++) at[t] = 0.f;
    for (int k = tid; k < H; k += 256) {
        float qv = g_q[k];
#pragma unroll
        for (int t = 0; t < T; t++) at[t] += qv * g_enc[t * H + k];
    }
#pragma unroll
    for (int t = 0; t < T; t++)
        for (int off = 16; off > 0; off >>= 1)
            at[t] += __shfl_down_sync(0xffffffffu, at[t], off);
    __shared__ float s2[T * 8];
    if (lane == 0) {
#pragma unroll
        for (int t = 0; t < T; t++) s2[t * 8 + warp] = at[t];
    }
    __syncthreads();
    __shared__ float sa[T];
    if (tid == 0) {
        float sc[T];
        float m = -INFINITY;
#pragma unroll
        for (int t = 0; t < T; t++) {
            float v = 0.f;
#pragma unroll
            for (int w = 0; w < 8; w++) v += s2[t * 8 + w];
            sc[t] = v;
            m = fmaxf(m, v);
        }
        float sum = 0.f;
#pragma unroll
        for (int t = 0; t < T; t++) { float e = expf(sc[t] - m); sa[t] = e; sum += e; }
#pragma unroll
        for (int t = 0; t < T; t++) sa[t] /= sum;
    }
    __syncthreads();
    for (int k = tid; k < H; k += 256) {
        float v = 0.f;
#pragma unroll
        for (int t = 0; t < T; t++) v += sa[t] * g_enc[t * H + k];
        g_ctx[k] = v;
    }
}

// ------- decoder part 1 (prev-independent) --------------------------------
__global__ void k_dec_pre(const float* __restrict__ w_ih,
                          const float* __restrict__ w_hh, int bi) {
    int tid  = threadIdx.x;
    int warp = tid >> 5;
    int lane = tid & 31;
    int j    = blockIdx.x * 2 + (warp >> 2);
    int gate = warp & 3;

    const float4* h4 = (const float4*)g_h[bi];
    const float4* c4 = (const float4*)g_ctx;
    const float4* wi = (const float4*)w_ih + (size_t)(gate * H + j) * 512 + 256;
    const float4* wh = (const float4*)w_hh + (size_t)(gate * H + j) * 256;

    float acc = 0.f;
#pragma unroll
    for (int i = 0; i < 8; i++) {
        int k = lane + 32 * i;
        acc += dot4(wi[k], c4[k]);
        acc += dot4(wh[k], h4[k]);
    }
    for (int off = 16; off > 0; off >>= 1)
        acc += __shfl_down_sync(0xffffffffu, acc, off);
    if (lane == 0) g_gate[gate * H + j] = acc;
}

// ------- decoder part 2: prev term + cell update; saves h into history ----
__global__ void k_dec_fin(const float* __restrict__ w_ih,
                          const float* __restrict__ b_ih,
                          const float* __restrict__ b_hh,
                          int bi, int step) {
    int tid  = threadIdx.x;
    int warp = tid >> 5;
    int lane = tid & 31;
    int j    = blockIdx.x * 2 + (warp >> 2);
    int gate = warp & 3;

    const float4* p4 = (const float4*)g_prev;
    const float4* wi = (const float4*)w_ih + (size_t)(gate * H + j) * 512;

    float acc = 0.f;
#pragma unroll
    for (int i = 0; i < 8; i++) {
        int k = lane + 32 * i;
        float4 v = p4[k];
        v.x = fmaxf(v.x, 0.f); v.y = fmaxf(v.y, 0.f);
        v.z = fmaxf(v.z, 0.f); v.w = fmaxf(v.w, 0.f);
        acc += dot4(wi[k], v);
    }
    for (int off = 16; off > 0; off >>= 1)
        acc += __shfl_down_sync(0xffffffffu, acc, off);

    __shared__ float s[8];
    if (lane == 0) s[warp] = acc;
    __syncthreads();
    if (tid < 2) {
        int u = blockIdx.x * 2 + tid;
        float gi = s[tid * 4 + 0] + g_gate[0 * H + u] + b_ih[u]         + b_hh[u];
        float gf = s[tid * 4 + 1] + g_gate[1 * H + u] + b_ih[H + u]     + b_hh[H + u];
        float gg = s[tid * 4 + 2] + g_gate[2 * H + u] + b_ih[2 * H + u] + b_hh[2 * H + u];
        float go = s[tid * 4 + 3] + g_gate[3 * H + u] + b_ih[3 * H + u] + b_hh[3 * H + u];
        float i_ = sigm(gi), f_ = sigm(gf), g_ = tanhf(gg), o_ = sigm(go);
        float cn = f_ * g_c[bi][u] + i_ * g_;
        float hn = o_ * tanhf(cn);
        g_c[1 - bi][u] = cn;
        g_h[1 - bi][u] = hn;
        g_hist[step][u] = hn;
    }
}

// ------- exact-argmax tail (runs in last block of conv/screen grid) -------
__device__ __forceinline__ void final_argmax_tail(
        const float* __restrict__ w32, const float* __restrict__ out_b,
        int hb, const float* __restrict__ embeds,
        float* __restrict__ out_ids, int write_ids, int step, int nb,
        int use_bound) {
    int tid  = threadIdx.x;
    int lane = tid & 31;
    int warp = tid >> 5;

    __shared__ float s_h1;
    if (use_bound) {
        float h1 = 0.f;
        for (int k = tid; k < H; k += 256) h1 += fabsf(g_h[hb][k]);
        for (int off = 16; off > 0; off >>= 1)
            h1 += __shfl_down_sync(0xffffffffu, h1, off);
        __shared__ float sh[8];
        if (lane == 0) sh[warp] = h1;
        __syncthreads();
        if (tid == 0) {
            float v = 0.f;
#pragma unroll
            for (int w = 0; w < 8; w++) v += sh[w];
            s_h1 = v;
        }
        __syncthreads();
    }
    float B = use_bound
            ? 6.5e-4f * __int_as_float(g_wmax_bits) * s_h1 + 1e-6f
            : 0.f;

    float best = -INFINITY; int bidx = 0x7fffffff;
    for (int i = tid; i < 2 * nb; i += 256) {
        float v = g_pval[i]; int ix = g_pidx[i];
        if (v > best || (v == best && ix < bidx)) { best = v; bidx = ix; }
    }
    __shared__ float sv[256]; __shared__ int si[256];
    sv[tid] = best; si[tid] = bidx;
    __syncthreads();
    for (int off = 128; off > 0; off >>= 1) {
        if (tid < off) {
            float v2 = sv[tid + off]; int i2 = si[tid + off];
            if (v2 > sv[tid] || (v2 == sv[tid] && i2 < si[tid])) { sv[tid] = v2; si[tid] = i2; }
        }
        __syncthreads();
    }
    float thresh = sv[0] - 2.f * B;

    __shared__ int cand[64];
    __shared__ int s_nc;
    __shared__ float cval[64];
    if (tid == 0) s_nc = 0;
    __syncthreads();
    for (int i = tid; i < 2 * nb; i += 256) {
        if (g_pval[i] >= thresh && g_pidx[i] < V) {
            int slot = atomicAdd(&s_nc, 1);
            if (slot < 64) cand[slot] = g_pidx[i];
        }
    }
    __syncthreads();
    int nc = min(s_nc, 64);

    const float4* h4f = (const float4*)g_h[hb];
    for (int c = warp; c < nc; c += 8) {
        int r = cand[c];
        const float4* wr = (const float4*)(w32 + (size_t)r * H);
        float acc = 0.f;
#pragma unroll
        for (int i = 0; i < 8; i++) {
            int k = lane + 32 * i;
            acc += dot4(wr[k], h4f[k]);
        }
        for (int off = 16; off > 0; off >>= 1)
            acc += __shfl_down_sync(0xffffffffu, acc, off);
        if (lane == 0) cval[c] = acc + out_b[r];
    }
    __syncthreads();
    __shared__ int s_idx;
    if (tid == 0) {
        float bv2 = -INFINITY; int bi2 = 0x7fffffff;
        for (int c = 0; c < nc; c++) {
            if (cval[c] > bv2 || (cval[c] == bv2 && cand[c] < bi2)) {
                bv2 = cval[c]; bi2 = cand[c];
            }
        }
        s_idx = bi2;
    }
    __syncthreads();
    int idx = s_idx;
    for (int k = tid; k < H; k += 256)
        g_prev[k] = embeds[(size_t)idx * H + k];
    if (tid == 0 && write_ids) out_ids[step] = (float)idx;
}

__device__ __forceinline__ void publish_top2(
        int tid, const float* bv, const int* bix, int n,
        int blockId, int nblocks, int* s_last) {
    if (tid == 0) {
        float v1 = -INFINITY, v2 = -INFINITY; int i1 = 0x7fffffff, i2 = 0x7fffffff;
        for (int w = 0; w < n; w++) {
            float v = bv[w]; int ix = bix[w];
            if (v > v1 || (v == v1 && ix < i1)) { v2 = v1; i2 = i1; v1 = v; i1 = ix; }
            else if (v > v2 || (v == v2 && ix < i2)) { v2 = v; i2 = ix; }
        }
        g_pval[2 * blockId] = v1;     g_pidx[2 * blockId] = i1;
        g_pval[2 * blockId + 1] = v2; g_pidx[2 * blockId + 1] = i2;
        __threadfence();
        *s_last = (atomicAdd(&g_cnt2, 1u) == nblocks - 1);
    }
}

// ------- step 0: exact fp32 logits + write fp16 sketch + max|w| ----------
__global__ void k_logits_conv(const float* __restrict__ w32,
                              const float* __restrict__ out_b,
                              int hb, float* __restrict__ out,
                              const float* __restrict__ embeds,
                              float* __restrict__ out_ids, int write_ids, int step) {
    int tid  = threadIdx.x;
    int lane = tid & 31;
    int warp = tid >> 5;
    int r0 = blockIdx.x * 16 + warp * 2;

    const float4* h4 = (const float4*)g_h[hb];
    float4 hreg[8];
#pragma unroll
    for (int i = 0; i < 4; i++) {
        int c = lane + 32 * i;
        hreg[2 * i]     = h4[2 * c];
        hreg[2 * i + 1] = h4[2 * c + 1];
    }

    float a0 = 0.f, a1 = 0.f, wm = 0.f;
#pragma unroll
    for (int row = 0; row < 2; row++) {
        int r = r0 + row;
        if (r >= V) break;
        const float4* wr = (const float4*)(w32 + (size_t)r * H);
        uint4* w16 = (uint4*)(g_w16 + (size_t)r * H);
        float acc = 0.f;
#pragma unroll
        for (int i = 0; i < 4; i++) {
            int c = lane + 32 * i;
            float4 wa4 = __ldcs(wr + 2 * c);
            float4 wb4 = __ldcs(wr + 2 * c + 1);
            acc += dot4(wa4, hreg[2 * i]) + dot4(wb4, hreg[2 * i + 1]);
            wm = fmaxf(wm, fmaxf(fmaxf(fabsf(wa4.x), fabsf(wa4.y)),
                                 fmaxf(fabsf(wa4.z), fabsf(wa4.w))));
            wm = fmaxf(wm, fmaxf(fmaxf(fabsf(wb4.x), fabsf(wb4.y)),
                                 fmaxf(fabsf(wb4.z), fabsf(wb4.w))));
            __half2 p0 = __floats2half2_rn(wa4.x, wa4.y);
            __half2 p1 = __floats2half2_rn(wa4.z, wa4.w);
            __half2 p2 = __floats2half2_rn(wb4.x, wb4.y);
            __half2 p3 = __floats2half2_rn(wb4.z, wb4.w);
            uint4 pk;
            pk.x = *(unsigned int*)&p0; pk.y = *(unsigned int*)&p1;
            pk.z = *(unsigned int*)&p2; pk.w = *(unsigned int*)&p3;
            __stcs(w16 + c, pk);
        }
        if (row == 0) a0 = acc; else a1 = acc;
    }
    for (int off = 16; off > 0; off >>= 1) {
        a0 += __shfl_down_sync(0xffffffffu, a0, off);
        a1 += __shfl_down_sync(0xffffffffu, a1, off);
        wm = fmaxf(wm, __shfl_down_sync(0xffffffffu, wm, off));
    }

    __shared__ float bv[16];
    __shared__ int   bix[16];
    __shared__ float swm[8];
    __shared__ int   s_last;
    if (lane == 0) {
        int r1 = r0 + 1;
        float l0 = -INFINITY, l1 = -INFINITY;
        if (r0 < V) { l0 = a0 + out_b[r0]; __stcs(out + r0, l0); }
        if (r1 < V) { l1 = a1 + out_b[r1]; __stcs(out + r1, l1); }
        bv[warp * 2] = l0;     bix[warp * 2] = r0;
        bv[warp * 2 + 1] = l1; bix[warp * 2 + 1] = r1;
        swm[warp] = wm;
    }
    __syncthreads();
    if (tid == 0) {
        float m = 0.f;
#pragma unroll
        for (int w = 0; w < 8; w++) m = fmaxf(m, swm[w]);
        atomicMax(&g_wmax_bits, __float_as_int(m));
    }
    publish_top2(tid, bv, bix, 16, blockIdx.x, gridDim.x, &s_last);
    __syncthreads();
    if (!s_last) return;
    if (tid == 0) g_cnt2 = 0;
    final_argmax_tail(w32, out_b, hb, embeds, out_ids, write_ids, step,
                      gridDim.x, /*use_bound=*/0);
}

// ------- steps 1..9: fp16 argmax screen, 4 rows/warp (no logits write) ----
__global__ void k_screen(const float* __restrict__ w32,
                         const float* __restrict__ out_b,
                         int hb, const float* __restrict__ embeds,
                         float* __restrict__ out_ids, int write_ids, int step) {
    int tid  = threadIdx.x;
    int lane = tid & 31;
    int warp = tid >> 5;
    int r0 = blockIdx.x * 32 + warp * 4;

    const float4* h4 = (const float4*)g_h[hb];
    float4 hreg[8];
#pragma unroll
    for (int i = 0; i < 4; i++) {
        int c = lane + 32 * i;
        hreg[2 * i]     = h4[2 * c];
        hreg[2 * i + 1] = h4[2 * c + 1];
    }

    float acc[4] = {0.f, 0.f, 0.f, 0.f};
    const uint4* wr[4];
    bool vv[4];
#pragma unroll
    for (int r = 0; r < 4; r++) {
        vv[r] = (r0 + r) < V;
        wr[r] = (const uint4*)(g_w16 + (size_t)(r0 + r) * H);
    }
#pragma unroll
    for (int i = 0; i < 4; i++) {
        int k = lane + 32 * i;
        float4 ha = hreg[2 * i], hb2 = hreg[2 * i + 1];
#pragma unroll
        for (int r = 0; r < 4; r++) {
            if (!vv[r]) continue;
            uint4 u = __ldcs(wr[r] + k);
            float2 f;
            float a = 0.f;
            f = __half22float2(*(const __half2*)&u.x);
            a += f.x * ha.x + f.y * ha.y;
            f = __half22float2(*(const __half2*)&u.y);
            a += f.x * ha.z + f.y * ha.w;
            f = __half22float2(*(const __half2*)&u.z);
            a += f.x * hb2.x + f.y * hb2.y;
            f = __half22float2(*(const __half2*)&u.w);
            a += f.x * hb2.z + f.y * hb2.w;
            acc[r] += a;
        }
    }
#pragma unroll
    for (int r = 0; r < 4; r++)
        for (int off = 16; off > 0; off >>= 1)
            acc[r] += __shfl_down_sync(0xffffffffu, acc[r], off);

    __shared__ float bv[32];
    __shared__ int   bix[32];
    __shared__ int   s_last;
    if (lane == 0) {
#pragma unroll
        for (int r = 0; r < 4; r++) {
            int rr = r0 + r;
            bv[warp * 4 + r]  = vv[r] ? acc[r] + out_b[rr] : -INFINITY;
            bix[warp * 4 + r] = rr;
        }
    }
    __syncthreads();
    publish_top2(tid, bv, bix, 32, blockIdx.x, gridDim.x, &s_last);
    __syncthreads();
    if (!s_last) return;
    if (tid == 0) g_cnt2 = 0;
    final_argmax_tail(w32, out_b, hb, embeds, out_ids, write_ids, step,
                      gridDim.x, /*use_bound=*/1);
}

// ------- batched exact fp32 logits for steps 1..9 (out_w read ONCE) ------
__global__ void k_logits_batch(const float* __restrict__ w32,
                               const float* __restrict__ out_b,
                               float* __restrict__ out) {
    __shared__ float4 hsh[TB][256];   // 9 x 1024 floats = 36KB
    int tid  = threadIdx.x;
    int lane = tid & 31;
    int warp = tid >> 5;

    for (int idx = tid; idx < TB * 256; idx += 256) {
        int t = idx >> 8, k = idx & 255;
        hsh[t][k] = ((const float4*)g_hist[t + 1])[k];
    }
    __syncthreads();

    int r0 = blockIdx.x * 16 + warp * 2;
    int r1 = r0 + 1;
    bool v0 = r0 < V, v1 = r1 < V;
    const float4* w0 = (const float4*)(w32 + (size_t)r0 * H);
    const float4* w1 = (const float4*)(w32 + (size_t)r1 * H);

    float acc0[TB], acc1[TB];
#pragma unroll
    for (int t = 0; t < TB; t++) { acc0[t] = 0.f; acc1[t] = 0.f; }

#pragma unroll
    for (int i = 0; i < 8; i++) {
        int k = lane + 32 * i;
        float4 a = v0 ? __ldcs(w0 + k) : make_float4(0.f, 0.f, 0.f, 0.f);
        float4 b = v1 ? __ldcs(w1 + k) : make_float4(0.f, 0.f, 0.f, 0.f);
#pragma unroll
        for (int t = 0; t < TB; t++) {
            float4 h = hsh[t][k];
            acc0[t] += dot4(a, h);
            acc1[t] += dot4(b, h);
        }
    }
#pragma unroll
    for (int t = 0; t < TB; t++) {
        for (int off = 16; off > 0; off >>= 1) {
            acc0[t] += __shfl_down_sync(0xffffffffu, acc0[t], off);
            acc1[t] += __shfl_down_sync(0xffffffffu, acc1[t], off);
        }
    }
    if (lane == 0) {
        float b0 = v0 ? out_b[r0] : 0.f;
        float b1 = v1 ? out_b[r1] : 0.f;
#pragma unroll
        for (int t = 0; t < TB; t++) {
            if (v0) __stcs(out + (size_t)(t + 1) * V + r0, acc0[t] + b0);
            if (v1) __stcs(out + (size_t)(t + 1) * V + r1, acc1[t] + b1);
        }
    }
}

// ---------------- launch ---------------------------------------------------
extern "C" void kernel_launch(void* const* d_in, const int* in_sizes, int n_in,
                              void* d_out, int out_size) {
    const void*  seq    = d_in[0];
    const float* embeds = (const float*)d_in[1];
    const float* ew_ih  = (const float*)d_in[2];
    const float* ew_hh  = (const float*)d_in[3];
    const float* eb_ih  = (const float*)d_in[4];
    const float* eb_hh  = (const float*)d_in[5];
    const float* dw_ih  = (const float*)d_in[6];
    const float* dw_hh  = (const float*)d_in[7];
    const float* db_ih  = (const float*)d_in[8];
    const float* db_hh  = (const float*)d_in[9];
    const float* out_w  = (const float*)d_in[10];
    const float* out_b  = (const float*)d_in[11];
    const float* wa     = (const float*)d_in[12];
    float* out = (float*)d_out;

    int write_ids = (out_size >= T * V + T) ? 1 : 0;

    static cudaStream_t s2 = nullptr;
    static cudaEvent_t evFork = nullptr, evJoin = nullptr;
    if (!s2) {
        int loPri, hiPri;
        cudaDeviceGetStreamPriorityRange(&loPri, &hiPri);
        cudaStreamCreateWithPriority(&s2, cudaStreamNonBlocking, hiPri);
        cudaEventCreateWithFlags(&evFork, cudaEventDisableTiming);
        cudaEventCreateWithFlags(&evJoin, cudaEventDisableTiming);
    }

    k_init<<<256, 256>>>(seq, out, out_size);
    k_xproj<<<H / 2, 256>>>(ew_ih, eb_ih, eb_hh, embeds);
    for (int s = 0; s < T; s++)
        k_lstm_enc<<<H / 2, 256>>>(ew_hh, s, s & 1);

    // step 0 front end
    k_qattn<<<32, 256>>>(wa, 0);
    k_dec_pre<<<H / 2, 256>>>(dw_ih, dw_hh, 0);
    k_dec_fin<<<H / 2, 256>>>(dw_ih, db_ih, db_hh, 0, 0);

    for (int d = 0; d < T; d++) {
        int bi = d & 1;
        if (d + 1 < T) {
            cudaEventRecord(evFork, 0);          // after dec_fin(d)
            cudaStreamWaitEvent(s2, evFork, 0);
            k_qattn<<<32, 256, 0, s2>>>(wa, (d + 1) & 1);
            k_dec_pre<<<H / 2, 256, 0, s2>>>(dw_ih, dw_hh, (d + 1) & 1);
            cudaEventRecord(evJoin, s2);
        }
        if (d == 0)
            k_logits_conv<<<NLB_F, 256>>>(out_w, out_b, 1 - bi, out,
                                          embeds, out + (size_t)T * V,
                                          write_ids, 0);
        else
            k_screen<<<NLB_S, 256>>>(out_w, out_b, 1 - bi,
                                     embeds, out + (size_t)T * V,
                                     write_ids, d);
        if (d + 1 < T) {
            cudaStreamWaitEvent(0, evJoin, 0);
            k_dec_fin<<<H / 2, 256>>>(dw_ih, db_ih, db_hh, (d + 1) & 1, d + 1);
        }
    }

    // one exact fp32 GEMM for all step 1..9 logits (out_w read once)
    k_logits_batch<<<NLB_F, 256>>>(out_w, out_b, out);
}

// round 13
// speedup vs baseline: 1.2181x; 1.2181x over previous
#include <cuda_runtime.h>
#include <math.h>

#define V 50257
#define H 1024
#define T 10
#define LROWS 32
#define NLB ((V + LROWS - 1) / LROWS)   // 1571 logits blocks (512 threads each)

// ---------------- device scratch (no allocations allowed) ----------------
__device__ __align__(16) float g_h[2][H];
__device__ __align__(16) float g_c[2][H];
__device__ __align__(16) float g_enc[T * H];
__device__ __align__(16) float g_prev[H];
__device__ __align__(16) float g_q[H];
__device__ __align__(16) float g_ctx[H];
__device__ __align__(16) float g_gate[4 * H];    // decoder partial gate sums
__device__ __align__(16) float g_xproj[T * 4 * H]; // enc W_ih@x_t + biases
__device__ int   g_tok[T];
__device__ float g_pval[NLB + 32];
__device__ int   g_pidx[NLB + 32];
__device__ unsigned int g_cnt1;
__device__ unsigned int g_cnt2;

__device__ __forceinline__ float sigm(float x) { return 1.f / (1.f + expf(-x)); }
__device__ __forceinline__ float dot4(float4 a, float4 b) {
    return a.x * b.x + a.y * b.y + a.z * b.z + a.w * b.w;
}

// ---------------- init: tokens, states, poison-safe tail zero -------------
__global__ void k_init(const void* __restrict__ seq_raw,
                       float* __restrict__ out, int out_size) {
    int tid = blockIdx.x * blockDim.x + threadIdx.x;
    if (tid == 0) {
        const long long* s64 = (const long long*)seq_raw;
        bool ok64 = true;
        for (int i = 0; i < T; i++) {
            long long v = s64[i];
            if (v < 0 || v >= V) { ok64 = false; break; }
        }
        const int* s32 = (const int*)seq_raw;
        for (int i = 0; i < T; i++) g_tok[i] = ok64 ? (int)s64[i] : s32[i];
        g_cnt1 = 0; g_cnt2 = 0;
    }
    int stride = gridDim.x * blockDim.x;
    for (int i = tid; i < H; i += stride) {
        g_h[0][i] = 0.f; g_c[0][i] = 0.f; g_prev[i] = 0.f;
    }
    // logits region [0, T*V) is fully overwritten each step; zero only the tail
    for (int i = T * V + tid; i < out_size; i += stride) out[i] = 0.f;
}

// ------- hoisted input projection: xproj[t] = W_ih x_t + b_ih + b_hh ------
__global__ void k_xproj(const float* __restrict__ w_ih,
                        const float* __restrict__ b_ih,
                        const float* __restrict__ b_hh,
                        const float* __restrict__ embeds) {
    int tid  = threadIdx.x;
    int warp = tid >> 5;
    int lane = tid & 31;
    int j    = blockIdx.x * 2 + (warp >> 2);
    int gate = warp & 3;

    const float4* wi = (const float4*)w_ih + (size_t)(gate * H + j) * 256;
    float4 w[8];
#pragma unroll
    for (int i = 0; i < 8; i++) w[i] = wi[lane + 32 * i];

    float acc[T];
#pragma unroll
    for (int t = 0; t < T; t++) {
        const float4* x4 = (const float4*)(embeds + (size_t)g_tok[t] * H);
        float a = 0.f;
#pragma unroll
        for (int i = 0; i < 8; i++) a += dot4(w[i], x4[lane + 32 * i]);
        acc[t] = a;
    }
#pragma unroll
    for (int t = 0; t < T; t++)
        for (int off = 16; off > 0; off >>= 1)
            acc[t] += __shfl_down_sync(0xffffffffu, acc[t], off);
    if (lane == 0) {
        int row = gate * H + j;
        float b = b_ih[row] + b_hh[row];
#pragma unroll
        for (int t = 0; t < T; t++)
            g_xproj[t * 4 * H + row] = acc[t] + b;
    }
}

// ------- encoder LSTM step: hidden part only (W_hh@h), 16MB/step ---------
__global__ void k_lstm_enc(const float* __restrict__ w_hh,
                           int step, int bi) {
    int tid  = threadIdx.x;
    int warp = tid >> 5;
    int lane = tid & 31;
    int j    = blockIdx.x * 2 + (warp >> 2);
    int gate = warp & 3;

    const float4* h4 = (const float4*)g_h[bi];
    const float4* wh = (const float4*)w_hh + (size_t)(gate * H + j) * 256;

    float acc = 0.f;
#pragma unroll
    for (int i = 0; i < 8; i++) {
        int k = lane + 32 * i;
        acc += dot4(wh[k], h4[k]);
    }
    for (int off = 16; off > 0; off >>= 1)
        acc += __shfl_down_sync(0xffffffffu, acc, off);

    __shared__ float s[8];
    if (lane == 0) s[warp] = acc;
    __syncthreads();
    if (tid < 2) {
        int u = blockIdx.x * 2 + tid;
        const float* xp = g_xproj + step * 4 * H;
        float gi = s[tid * 4 + 0] + xp[u];
        float gf = s[tid * 4 + 1] + xp[H + u];
        float gg = s[tid * 4 + 2] + xp[2 * H + u];
        float go = s[tid * 4 + 3] + xp[3 * H + u];
        float i_ = sigm(gi), f_ = sigm(gf), g_ = tanhf(gg), o_ = sigm(go);
        float cn = f_ * g_c[bi][u] + i_ * g_;
        float hn = o_ * tanhf(cn);
        g_c[1 - bi][u] = cn;
        g_h[1 - bi][u] = hn;
        g_enc[step * H + u] = hn;
    }
}

// ---------------- q = wa^T h, then last block does softmax+ctx -----------
__global__ void k_qattn(const float* __restrict__ wa, int bi) {
    int tid  = threadIdx.x;
    int lane = tid & 31;
    int warp = tid >> 5;
    int col  = blockIdx.x * 32 + lane;
    const float* h = g_h[bi];

    float acc = 0.f;
    for (int i = warp; i < H; i += 8) acc += h[i] * wa[(size_t)i * H + col];
    __shared__ float s[256];
    s[tid] = acc;
    __syncthreads();
    for (int off = 128; off >= 32; off >>= 1) {
        if (tid < off) s[tid] += s[tid + off];
        __syncthreads();
    }
    if (tid < 32) g_q[col] = s[tid];

    __shared__ int s_last;
    __threadfence();
    if (tid == 0) s_last = (atomicAdd(&g_cnt1, 1u) == gridDim.x - 1);
    __syncthreads();
    if (!s_last) return;
    if (tid == 0) g_cnt1 = 0;

    float at[T];
#pragma unroll
    for (int t = 0; t < T; t++) at[t] = 0.f;
    for (int k = tid; k < H; k += 256) {
        float qv = g_q[k];
#pragma unroll
        for (int t = 0; t < T; t++) at[t] += qv * g_enc[t * H + k];
    }
#pragma unroll
    for (int t = 0; t < T; t++)
        for (int off = 16; off > 0; off >>= 1)
            at[t] += __shfl_down_sync(0xffffffffu, at[t], off);
    __shared__ float s2[T * 8];
    if (lane == 0) {
#pragma unroll
        for (int t = 0; t < T; t++) s2[t * 8 + warp] = at[t];
    }
    __syncthreads();
    __shared__ float sa[T];
    if (tid == 0) {
        float sc[T];
        float m = -INFINITY;
#pragma unroll
        for (int t = 0; t < T; t++) {
            float v = 0.f;
#pragma unroll
            for (int w = 0; w < 8; w++) v += s2[t * 8 + w];
            sc[t] = v;
            m = fmaxf(m, v);
        }
        float sum = 0.f;
#pragma unroll
        for (int t = 0; t < T; t++) { float e = expf(sc[t] - m); sa[t] = e; sum += e; }
#pragma unroll
        for (int t = 0; t < T; t++) sa[t] /= sum;
    }
    __syncthreads();
    for (int k = tid; k < H; k += 256) {
        float v = 0.f;
#pragma unroll
        for (int t = 0; t < T; t++) v += sa[t] * g_enc[t * H + k];
        g_ctx[k] = v;
    }
}

// ------- decoder part 1 (prev-independent): g_gate = Wih[:,H:]ctx + Whh h -
__global__ void k_dec_pre(const float* __restrict__ w_ih,  // (4H, 2H)
                          const float* __restrict__ w_hh,  // (4H, H)
                          int bi) {
    int tid  = threadIdx.x;
    int warp = tid >> 5;
    int lane = tid & 31;
    int j    = blockIdx.x * 2 + (warp >> 2);
    int gate = warp & 3;

    const float4* h4 = (const float4*)g_h[bi];
    const float4* c4 = (const float4*)g_ctx;
    const float4* wi = (const float4*)w_ih + (size_t)(gate * H + j) * 512 + 256;
    const float4* wh = (const float4*)w_hh + (size_t)(gate * H + j) * 256;

    float acc = 0.f;
#pragma unroll
    for (int i = 0; i < 8; i++) {
        int k = lane + 32 * i;
        acc += dot4(wi[k], c4[k]);
        acc += dot4(wh[k], h4[k]);
    }
    for (int off = 16; off > 0; off >>= 1)
        acc += __shfl_down_sync(0xffffffffu, acc, off);
    if (lane == 0) g_gate[gate * H + j] = acc;
}

// ------- decoder part 2 (prev term + cell update) -------------------------
__global__ void k_dec_fin(const float* __restrict__ w_ih,  // (4H, 2H)
                          const float* __restrict__ b_ih,
                          const float* __restrict__ b_hh,
                          int bi) {
    int tid  = threadIdx.x;
    int warp = tid >> 5;
    int lane = tid & 31;
    int j    = blockIdx.x * 2 + (warp >> 2);
    int gate = warp & 3;

    const float4* p4 = (const float4*)g_prev;
    const float4* wi = (const float4*)w_ih + (size_t)(gate * H + j) * 512;

    float acc = 0.f;
#pragma unroll
    for (int i = 0; i < 8; i++) {
        int k = lane + 32 * i;
        float4 v = p4[k];
        v.x = fmaxf(v.x, 0.f); v.y = fmaxf(v.y, 0.f);
        v.z = fmaxf(v.z, 0.f); v.w = fmaxf(v.w, 0.f);
        acc += dot4(wi[k], v);
    }
    for (int off = 16; off > 0; off >>= 1)
        acc += __shfl_down_sync(0xffffffffu, acc, off);

    __shared__ float s[8];
    if (lane == 0) s[warp] = acc;
    __syncthreads();
    if (tid < 2) {
        int u = blockIdx.x * 2 + tid;
        float gi = s[tid * 4 + 0] + g_gate[0 * H + u] + b_ih[u]         + b_hh[u];
        float gf = s[tid * 4 + 1] + g_gate[1 * H + u] + b_ih[H + u]     + b_hh[H + u];
        float gg = s[tid * 4 + 2] + g_gate[2 * H + u] + b_ih[2 * H + u] + b_hh[2 * H + u];
        float go = s[tid * 4 + 3] + g_gate[3 * H + u] + b_ih[3 * H + u] + b_hh[3 * H + u];
        float i_ = sigm(gi), f_ = sigm(gf), g_ = tanhf(gg), o_ = sigm(go);
        float cn = f_ * g_c[bi][u] + i_ * g_;
        float hn = o_ * tanhf(cn);
        g_c[1 - bi][u] = cn;
        g_h[1 - bi][u] = hn;
    }
}

// ---- logits: 512 threads, 16 warps x 2 rows (proven pattern), fused argmax
__global__ void __launch_bounds__(512) k_logits(
        const float* __restrict__ out_w,
        const float* __restrict__ out_b,
        int hb, float* __restrict__ out,
        const float* __restrict__ embeds,
        float* __restrict__ out_ids, int write_ids, int step) {
    int tid  = threadIdx.x;
    int lane = tid & 31;
    int warp = tid >> 5;                 // 16 warps, 2 rows each
    int r0 = blockIdx.x * LROWS + warp * 2;
    int r1 = r0 + 1;

    const float4* h4 = (const float4*)g_h[hb];
    float4 hv[8];
#pragma unroll
    for (int i = 0; i < 8; i++) hv[i] = h4[lane + 32 * i];

    float t0 = 0.f, t1 = 0.f;
    if (r0 < V) {
        const float4* w0 = (const float4*)(out_w + (size_t)r0 * H);
#pragma unroll
        for (int i = 0; i < 8; i++) t0 += dot4(__ldcs(w0 + lane + 32 * i), hv[i]);
    }
    if (r1 < V) {
        const float4* w1 = (const float4*)(out_w + (size_t)r1 * H);
#pragma unroll
        for (int i = 0; i < 8; i++) t1 += dot4(__ldcs(w1 + lane + 32 * i), hv[i]);
    }
    for (int off = 16; off > 0; off >>= 1) {
        t0 += __shfl_down_sync(0xffffffffu, t0, off);
        t1 += __shfl_down_sync(0xffffffffu, t1, off);
    }

    __shared__ float bv[32];
    __shared__ int   bix[32];
    __shared__ int   s_last;
    if (lane == 0) {
        float l0 = -INFINITY, l1 = -INFINITY;
        if (r0 < V) { l0 = t0 + out_b[r0]; __stcs(out + r0, l0); }
        if (r1 < V) { l1 = t1 + out_b[r1]; __stcs(out + r1, l1); }
        bv[warp * 2] = l0;     bix[warp * 2] = r0;
        bv[warp * 2 + 1] = l1; bix[warp * 2 + 1] = r1;
    }
    __syncthreads();
    if (tid == 0) {
        float best = bv[0]; int bj = bix[0];
#pragma unroll
        for (int w = 1; w < 32; w++)
            if (bv[w] > best) { best = bv[w]; bj = bix[w]; }
        g_pval[blockIdx.x] = best;
        g_pidx[blockIdx.x] = bj;
        __threadfence();
        s_last = (atomicAdd(&g_cnt2, 1u) == gridDim.x - 1);
    }
    __syncthreads();
    if (!s_last) return;
    if (tid == 0) g_cnt2 = 0;

    // -------- final argmax (first-max, matches jnp.argmax) + gather ------
    float best = -INFINITY;
    int bidx = 0x7fffffff;
    int nb = gridDim.x;
    for (int i = tid; i < nb; i += 512) {
        float v = g_pval[i]; int ix = g_pidx[i];
        if (v > best || (v == best && ix < bidx)) { best = v; bidx = ix; }
    }
    __shared__ float sv[512];
    __shared__ int   si[512];
    sv[tid] = best; si[tid] = bidx;
    __syncthreads();
    for (int off = 256; off > 0; off >>= 1) {
        if (tid < off) {
            float v2 = sv[tid + off]; int i2 = si[tid + off];
            if (v2 > sv[tid] || (v2 == sv[tid] && i2 < si[tid])) {
                sv[tid] = v2; si[tid] = i2;
            }
        }
        __syncthreads();
    }
    int idx = si[0];
    for (int k = tid; k < H; k += 512)
        g_prev[k] = embeds[(size_t)idx * H + k];
    if (tid == 0 && write_ids) out_ids[step] = (float)idx;
}

// ---------------- launch ---------------------------------------------------
extern "C" void kernel_launch(void* const* d_in, const int* in_sizes, int n_in,
                              void* d_out, int out_size) {
    const void*  seq    = d_in[0];
    const float* embeds = (const float*)d_in[1];
    const float* ew_ih  = (const float*)d_in[2];
    const float* ew_hh  = (const float*)d_in[3];
    const float* eb_ih  = (const float*)d_in[4];
    const float* eb_hh  = (const float*)d_in[5];
    const float* dw_ih  = (const float*)d_in[6];
    const float* dw_hh  = (const float*)d_in[7];
    const float* db_ih  = (const float*)d_in[8];
    const float* db_hh  = (const float*)d_in[9];
    const float* out_w  = (const float*)d_in[10];
    const float* out_b  = (const float*)d_in[11];
    const float* wa     = (const float*)d_in[12];
    float* out = (float*)d_out;

    int write_ids = (out_size >= T * V + T) ? 1 : 0;

    static cudaStream_t s2 = nullptr;
    static cudaEvent_t evFork = nullptr, evJoin = nullptr;
    if (!s2) {
        int loPri, hiPri;
        cudaDeviceGetStreamPriorityRange(&loPri, &hiPri);
        cudaStreamCreateWithPriority(&s2, cudaStreamNonBlocking, hiPri);
        cudaEventCreateWithFlags(&evFork, cudaEventDisableTiming);
        cudaEventCreateWithFlags(&evJoin, cudaEventDisableTiming);
    }

    k_init<<<256, 256>>>(seq, out, out_size);

    // hoisted input projection: W_ih read once for all T steps
    k_xproj<<<H / 2, 256>>>(ew_ih, eb_ih, eb_hh, embeds);

    // encoder recurrence: only W_hh@h per step (16MB)
    for (int s = 0; s < T; s++)
        k_lstm_enc<<<H / 2, 256>>>(ew_hh, s, s & 1);

    // step 0 front end
    k_qattn<<<32, 256>>>(wa, 0);
    k_dec_pre<<<H / 2, 256>>>(dw_ih, dw_hh, 0);
    k_dec_fin<<<H / 2, 256>>>(dw_ih, db_ih, db_hh, 0);

    for (int d = 0; d < T; d++) {
        int bi = d & 1;
        // overlap with logits(d): qattn(d+1) + dec_pre(d+1) on side stream
        if (d + 1 < T) {
            cudaEventRecord(evFork, 0);          // after dec_fin(d)
            cudaStreamWaitEvent(s2, evFork, 0);
            k_qattn<<<32, 256, 0, s2>>>(wa, (d + 1) & 1);
            k_dec_pre<<<H / 2, 256, 0, s2>>>(dw_ih, dw_hh, (d + 1) & 1);
            cudaEventRecord(evJoin, s2);
        }
        k_logits<<<NLB, 512>>>(out_w, out_b, 1 - bi,
                               out + (size_t)d * V,
                               embeds, out + (size_t)T * V,
                               write_ids, d);
        if (d + 1 < T) {
            cudaStreamWaitEvent(0, evJoin, 0);
            k_dec_fin<<<H / 2, 256>>>(dw_ih, db_ih, db_hh, (d + 1) & 1);
        }
    }
}